// round 17
// baseline (speedup 1.0000x reference)
#include <cuda_runtime.h>
#include <math.h>

#define N 4096
#define D 512

// ---------------- scratch (static __device__, per harness rules) -------------
__device__ float  g_fn[(size_t)N * D];      // normalized features, TF32-rounded
__device__ float  g_sims[(size_t)N * N];    // sims2[q1][q2], both axes label-sorted
__device__ float  g_ls[N];                  // sorted labels
__device__ int    g_perm[N];                // perm[q] = original index
__device__ int    g_ipos[N];                // ipos[i]  = position of i in sorted order
__device__ double g_loss[N];                // per-row losses

__device__ __forceinline__ float tf32_round(float x) {
    unsigned r;
    asm("cvt.rna.tf32.f32 %0, %1;" : "=r"(r) : "f"(x));
    return __uint_as_float(r);
}

// m16n8k8 TF32 MMA, fp32 accumulate
__device__ __forceinline__ void mma_tf32(float* c, const unsigned* a, const unsigned* b) {
    asm volatile(
        "mma.sync.aligned.m16n8k8.row.col.f32.tf32.tf32.f32 "
        "{%0,%1,%2,%3}, {%4,%5,%6,%7}, {%8,%9}, {%0,%1,%2,%3};\n"
        : "+f"(c[0]), "+f"(c[1]), "+f"(c[2]), "+f"(c[3])
        : "r"(a[0]), "r"(a[1]), "r"(a[2]), "r"(a[3]), "r"(b[0]), "r"(b[1]));
}

// ---------------- 1) fused sort (block 0) + row norm (blocks 1..512) ---------
__global__ __launch_bounds__(1024) void sortnorm_kernel(
        const float* __restrict__ labels, const float* __restrict__ X) {
    __shared__ float key[N];
    __shared__ int   idx[N];
    __shared__ float ws8[8][4];
    int tid = threadIdx.x;

    if (blockIdx.x == 0) {
        // ---- bitonic sort of labels (stable via index tie-break) ----
        for (int p = tid; p < N; p += 1024) { key[p] = labels[p]; idx[p] = p; }
        __syncthreads();
        for (int k = 2; k <= N; k <<= 1) {
            for (int j = k >> 1; j > 0; j >>= 1) {
                for (int p = tid; p < N; p += 1024) {
                    int q = p ^ j;
                    if (q > p) {
                        bool up = ((p & k) == 0);
                        float a = key[p], b = key[q];
                        bool swap = up ? (a > b || (a == b && idx[p] > idx[q]))
                                       : (a < b || (a == b && idx[p] < idx[q]));
                        if (swap) {
                            key[p] = b; key[q] = a;
                            int t2 = idx[p]; idx[p] = idx[q]; idx[q] = t2;
                        }
                    }
                }
                __syncthreads();
            }
        }
        for (int p = tid; p < N; p += 1024) {
            g_ls[p] = key[p];
            g_perm[p] = idx[p];
            g_ipos[idx[p]] = p;
        }
    } else {
        // ---- normalize 8 rows per block, 128 threads per row ----
        int rloc = tid >> 7;              // 0..7
        int rtid = tid & 127;             // 0..127
        int i = (blockIdx.x - 1) * 8 + rloc;
        const float4* xr = (const float4*)(X + (size_t)i * D);
        float4 v = xr[rtid];
        float ss = v.x * v.x + v.y * v.y + v.z * v.z + v.w * v.w;
        #pragma unroll
        for (int o = 16; o > 0; o >>= 1) ss += __shfl_xor_sync(0xffffffffu, ss, o);
        if ((rtid & 31) == 0) ws8[rloc][rtid >> 5] = ss;
        __syncthreads();
        float tot = ws8[rloc][0] + ws8[rloc][1] + ws8[rloc][2] + ws8[rloc][3];
        float nrm = sqrtf(tot);
        float4 o4 = make_float4(tf32_round(v.x / nrm), tf32_round(v.y / nrm),
                                tf32_round(v.z / nrm), tf32_round(v.w / nrm));
        ((float4*)g_fn)[(size_t)i * (D / 4) + rtid] = o4;
    }
}

// ---------------- 2) symmetric tensor-core GEMM + exp, cp.async 2-stage ------
#define KT 32
#define NKT (D / KT)
__global__ __launch_bounds__(256) void gemm_mma_sym_kernel() {
    extern __shared__ float dyn[];
    float (*As)[128][36] = (float(*)[128][36])dyn;                 // 2 stages
    float (*Bs)[128][36] = (float(*)[128][36])(dyn + 2 * 128 * 36);
    int* permA = (int*)(dyn + 4 * 128 * 36);
    int* permB = permA + 128;

    int tid = threadIdx.x;
    int lane = tid & 31, wid = tid >> 5;
    int warp_m = wid & 3;
    int warp_n = wid >> 2;

    int bi = 0, bj = 0;
    {
        int r = blockIdx.x;
        #pragma unroll 1
        for (int b = 0; b < 32; b++) {
            int cnt = 32 - b;
            if (r < cnt) { bi = b; bj = b + r; break; }
            r -= cnt;
        }
    }
    if (tid < 128) permA[tid] = g_perm[bi * 128 + tid];
    else           permB[tid - 128] = g_perm[bj * 128 + (tid - 128)];
    __syncthreads();

    int lrow[4], lc4[4];
    #pragma unroll
    for (int l = 0; l < 4; l++) {
        int j = tid + l * 256;
        lrow[l] = j >> 3;
        lc4[l]  = (j & 7) * 4;
    }

    float acc[2][8][4];
    #pragma unroll
    for (int mf = 0; mf < 2; mf++)
        #pragma unroll
        for (int nf = 0; nf < 8; nf++)
            #pragma unroll
            for (int r = 0; r < 4; r++) acc[mf][nf][r] = 0.0f;

    #pragma unroll
    for (int l = 0; l < 4; l++) {
        unsigned da = (unsigned)__cvta_generic_to_shared(&As[0][lrow[l]][lc4[l]]);
        asm volatile("cp.async.cg.shared.global [%0], [%1], 16;\n"
                     :: "r"(da), "l"(&g_fn[(size_t)permA[lrow[l]] * D + lc4[l]]));
        unsigned db = (unsigned)__cvta_generic_to_shared(&Bs[0][lrow[l]][lc4[l]]);
        asm volatile("cp.async.cg.shared.global [%0], [%1], 16;\n"
                     :: "r"(db), "l"(&g_fn[(size_t)permB[lrow[l]] * D + lc4[l]]));
    }
    asm volatile("cp.async.commit_group;\n");

    int stage = 0;
    for (int ki = 0; ki < NKT; ki++) {
        asm volatile("cp.async.wait_group 0;\n");
        __syncthreads();
        if (ki + 1 < NKT) {
            int kt = (ki + 1) * KT;
            int ns = stage ^ 1;
            #pragma unroll
            for (int l = 0; l < 4; l++) {
                unsigned da = (unsigned)__cvta_generic_to_shared(&As[ns][lrow[l]][lc4[l]]);
                asm volatile("cp.async.cg.shared.global [%0], [%1], 16;\n"
                             :: "r"(da), "l"(&g_fn[(size_t)permA[lrow[l]] * D + kt + lc4[l]]));
                unsigned db = (unsigned)__cvta_generic_to_shared(&Bs[ns][lrow[l]][lc4[l]]);
                asm volatile("cp.async.cg.shared.global [%0], [%1], 16;\n"
                             :: "r"(db), "l"(&g_fn[(size_t)permB[lrow[l]] * D + kt + lc4[l]]));
            }
            asm volatile("cp.async.commit_group;\n");
        }
        #pragma unroll
        for (int ks = 0; ks < 4; ks++) {
            int k0 = ks * 8 + (lane & 3);
            unsigned a[2][4], b[8][2];
            #pragma unroll
            for (int mf = 0; mf < 2; mf++) {
                int m0 = warp_m * 32 + mf * 16 + (lane >> 2);
                a[mf][0] = __float_as_uint(As[stage][m0][k0]);
                a[mf][1] = __float_as_uint(As[stage][m0 + 8][k0]);
                a[mf][2] = __float_as_uint(As[stage][m0][k0 + 4]);
                a[mf][3] = __float_as_uint(As[stage][m0 + 8][k0 + 4]);
            }
            #pragma unroll
            for (int nf = 0; nf < 8; nf++) {
                int n0 = warp_n * 64 + nf * 8 + (lane >> 2);
                b[nf][0] = __float_as_uint(Bs[stage][n0][k0]);
                b[nf][1] = __float_as_uint(Bs[stage][n0][k0 + 4]);
            }
            #pragma unroll
            for (int mf = 0; mf < 2; mf++)
                #pragma unroll
                for (int nf = 0; nf < 8; nf++)
                    mma_tf32(acc[mf][nf], a[mf], b[nf]);
        }
        __syncthreads();
        stage ^= 1;
    }

    #pragma unroll
    for (int mf = 0; mf < 2; mf++)
        #pragma unroll
        for (int nf = 0; nf < 8; nf++)
            #pragma unroll
            for (int r = 0; r < 4; r++)
                acc[mf][nf][r] = expf(acc[mf][nf][r] / 0.07f);

    #pragma unroll
    for (int mf = 0; mf < 2; mf++) {
        #pragma unroll
        for (int r = 0; r < 4; r++) {
            int row_local = warp_m * 32 + mf * 16 + (lane >> 2) + ((r >> 1) ? 8 : 0);
            int gq1 = bi * 128 + row_local;
            #pragma unroll
            for (int nf = 0; nf < 8; nf++) {
                int col_local = warp_n * 64 + nf * 8 + (lane & 3) * 2 + (r & 1);
                g_sims[(size_t)gq1 * N + bj * 128 + col_local] = acc[mf][nf][r];
            }
        }
    }

    if (bi != bj) {
        float (*stg)[129] = (float(*)[129])dyn;
        #pragma unroll 1
        for (int cc = 0; cc < 4; cc++) {
            __syncthreads();
            if (warp_m == cc) {
                #pragma unroll
                for (int mf = 0; mf < 2; mf++) {
                    #pragma unroll
                    for (int r = 0; r < 4; r++) {
                        int rr = mf * 16 + (lane >> 2) + ((r >> 1) ? 8 : 0);
                        #pragma unroll
                        for (int nf = 0; nf < 8; nf++) {
                            int col_local = warp_n * 64 + nf * 8 + (lane & 3) * 2 + (r & 1);
                            stg[rr][col_local] = acc[mf][nf][r];
                        }
                    }
                }
            }
            __syncthreads();
            for (int j = tid; j < 32 * 128; j += 256) {
                int rr = j & 31, cp = j >> 5;
                g_sims[(size_t)(bj * 128 + cp) * N + bi * 128 + cc * 32 + rr] = stg[rr][cp];
            }
        }
    }
}

// ---------------- 3) merge-order scan + terms --------------------------------
// Phase 1: merge-path walk (balanced, 8 events/thread) gathers sims + dists
//          into merge order.  Phase 2: double block-scan in MERGE order.
// Phase 3: den_k = (qt - rint(mpref[rend(k)]*8))*0.125 where rend(k) = end of
//          k's equal-dist run (sorted dists => run == old <= t window).
// Self-sim is never an event; qt = rint(total_tail*8) directly.
#define DISTL(i2) fabsf(li - lsh[ipos - 1 - (i2)])   /* Y[i2], i2 in [0,Lc) */
#define DISTR(j)  fabsf(li - lsh[ipos + 1 + (j)])    /* X[j],  j  in [0,Rc) */
__global__ __launch_bounds__(512) void scan_terms_kernel() {
    extern __shared__ char dsm[];
    double* mpref = (double*)dsm;                     // 32 KB  merge-order prefix
    float*  msims = (float*)(dsm + 32768);            // 16 KB  merge-order sims
    float*  mdist = (float*)(dsm + 49152);            // 16 KB  merge-order dists
    float*  lsh   = (float*)(dsm + 65536);            // 16 KB  sorted labels
    double* red   = (double*)(dsm + 81920);           // 4 KB
    __shared__ double warpsum[16];

    int q1 = blockIdx.x, tid = threadIdx.x;  // 512 threads
    const float* __restrict__ row = g_sims + (size_t)q1 * N;

    for (int p = tid; p < N; p += 512) lsh[p] = g_ls[p];
    __syncthreads();

    const float li = lsh[q1];
    const int ipos = q1;
    const int Lc = ipos;
    const int Rc = N - 1 - ipos;
    const int M  = N - 1;                  // 4095 merge events
    const float FINF = __int_as_float(0x7f800000);

    // ---- phase 1: merge walk, gather ----
    int k0 = tid * 8;
    {
        int kend = k0 + 8 < M ? k0 + 8 : M;
        if (k0 < M) {
            int lo = k0 - Rc; if (lo < 0) lo = 0;
            int hi = k0 < Lc ? k0 : Lc;
            while (lo < hi) {
                int mid = (lo + hi) >> 1;
                int iXc = k0 - mid;
                bool P = (iXc == 0) || (mid >= Lc) || (DISTR(iXc - 1) < DISTL(mid));
                if (P) hi = mid; else lo = mid + 1;
            }
            int iY = lo, iX = k0 - lo;
            float dX = (iX < Rc) ? DISTR(iX) : FINF;
            float dY = (iY < Lc) ? DISTL(iY) : FINF;
            for (int k = k0; k < kend; k++) {
                bool takeY = (iY < Lc) && (dY <= dX);
                int p; float t;
                if (takeY) {
                    t = dY; iY++; p = ipos - iY;
                    dY = (iY < Lc) ? DISTL(iY) : FINF;
                } else {
                    t = dX; iX++; p = ipos + iX;
                    dX = (iX < Rc) ? DISTR(iX) : FINF;
                }
                msims[k] = __ldg(&row[p]);
                mdist[k] = t;
            }
        }
    }
    if (tid == 511) { msims[N - 1] = 0.0f; mdist[N - 1] = FINF; }
    __syncthreads();

    // ---- phase 2: double block-scan over msims (merge order) ----
    double loc[8];
    double s = 0.0;
    #pragma unroll
    for (int k = 0; k < 8; k++) { s += (double)msims[tid * 8 + k]; loc[k] = s; }
    double ws = s;
    #pragma unroll
    for (int o = 1; o < 32; o <<= 1) {
        double v = __shfl_up_sync(0xffffffffu, ws, o);
        if ((tid & 31) >= o) ws += v;
    }
    if ((tid & 31) == 31) warpsum[tid >> 5] = ws;
    __syncthreads();
    if (tid < 16) {
        double w = warpsum[tid];
        #pragma unroll
        for (int o = 1; o < 16; o <<= 1) {
            double v = __shfl_up_sync(0x0000ffffu, w, o);
            if (tid >= o) w += v;
        }
        warpsum[tid] = w;
    }
    __syncthreads();
    double offset = ws - s;
    if (tid >= 32) offset += warpsum[(tid >> 5) - 1];
    #pragma unroll
    for (int k = 0; k < 8; k++) mpref[tid * 8 + k] = loc[k] + offset;
    __syncthreads();

    // ---- phase 3: denominators from merge prefix ----
    const double qt = rint(mpref[M - 1] * 8.0);
    double acc = 0.0;
    {
        int kend = k0 + 8 < M ? k0 + 8 : M;
        for (int k = k0; k < kend; k++) {
            float t = mdist[k];
            int ke = k;
            while (ke + 1 < M && mdist[ke + 1] == t) ke++;   // tie run (rare)
            double den = (qt - rint(mpref[ke] * 8.0)) * 0.125;
            if (den > 0.0) {
                acc += (double)__fdiv_rn(msims[k], (float)den);
            }
        }
    }

    red[tid] = acc;
    __syncthreads();
    for (int o = 256; o > 0; o >>= 1) {
        if (tid < o) red[tid] += red[tid + o];
        __syncthreads();
    }
    if (tid == 0) g_loss[q1] = red[0] / (double)(N - 1);
}

// ---------------- 4) deterministic final reduction ---------------------------
__global__ void final_reduce_kernel(float* __restrict__ out) {
    __shared__ double red[512];
    int tid = threadIdx.x;
    double s = 0.0;
    for (int k = tid; k < N; k += 512) s += g_loss[k];
    red[tid] = s;
    __syncthreads();
    for (int o = 256; o > 0; o >>= 1) {
        if (tid < o) red[tid] += red[tid + o];
        __syncthreads();
    }
    if (tid == 0) out[0] = (float)(red[0] / (double)N);
}

// ---------------- launcher ----------------------------------------------------
extern "C" void kernel_launch(void* const* d_in, const int* in_sizes, int n_in,
                              void* d_out, int out_size) {
    const float* features = (const float*)d_in[0];
    const float* labels   = (const float*)d_in[1];
    float* out = (float*)d_out;

    cudaFuncSetAttribute(gemm_mma_sym_kernel,
                         cudaFuncAttributeMaxDynamicSharedMemorySize, 74752);
    cudaFuncSetAttribute(scan_terms_kernel,
                         cudaFuncAttributeMaxDynamicSharedMemorySize, 86016);

    sortnorm_kernel<<<513, 1024>>>(labels, features);
    gemm_mma_sym_kernel<<<528, 256, 74752>>>();
    scan_terms_kernel<<<N, 512, 86016>>>();
    final_reduce_kernel<<<1, 512>>>(out);
}